// round 1
// baseline (speedup 1.0000x reference)
#include <cuda_runtime.h>

// UnPooling: stride-2 zero-insertion unpool.
// in:  [B=32, H=112, W=112, C=64] fp32
// out: [B=32, 224, 224, 64] fp32; out[b, 2h, 2w, c] = in[b, h, w, c], else 0.

constexpr int B  = 32;
constexpr int H  = 112;
constexpr int W  = 112;
constexpr int C  = 64;
constexpr int OH = H * 2;   // 224
constexpr int OW = W * 2;   // 224
constexpr int C4 = C / 4;   // 16 float4 per pixel

__global__ void __launch_bounds__(256)
unpool_zi_kernel(const float4* __restrict__ in, float4* __restrict__ out,
                 unsigned int n4)
{
    unsigned int i = blockIdx.x * 256u + threadIdx.x;
    if (i >= n4) return;

    unsigned int c4  = i & (C4 - 1);   // i % 16
    unsigned int pix = i >> 4;         // output pixel index

    unsigned int ow = pix % OW;
    unsigned int t  = pix / OW;
    unsigned int oh = t % OH;
    unsigned int b  = t / OH;

    float4 v = make_float4(0.f, 0.f, 0.f, 0.f);
    if (((oh | ow) & 1u) == 0u) {
        unsigned int iidx = ((b * H + (oh >> 1)) * W + (ow >> 1)) * C4 + c4;
        v = __ldcs(in + iidx);
    }
    __stcs(out + i, v);
}

extern "C" void kernel_launch(void* const* d_in, const int* in_sizes, int n_in,
                              void* d_out, int out_size)
{
    const float4* in  = (const float4*)d_in[0];
    float4*       out = (float4*)d_out;

    unsigned int n4 = (unsigned int)(out_size / 4);   // 25,690,112 float4s
    unsigned int grid = (n4 + 255u) / 256u;

    unpool_zi_kernel<<<grid, 256>>>(in, out, n4);
}

// round 2
// speedup vs baseline: 1.0037x; 1.0037x over previous
#include <cuda_runtime.h>

// UnPooling: stride-2 zero-insertion unpool.
// in:  [B=32, H=112, W=112, C=64] fp32
// out: [B=32, 224, 224, 64] fp32; out[b, 2h, 2w, c] = in[b, h, w, c], else 0.
//
// Grid (7, 224, 32): blockIdx.z = batch, blockIdx.y = output row,
// blockIdx.x = 512-float4 chunk within the row (row = 224*16 = 3584 float4).
// Odd output rows are entirely zero -> dedicated zero-fill fast path
// (no loads, no index math). Even rows: 2 float4 per thread, coalesced.

constexpr int B    = 32;
constexpr int H    = 112;
constexpr int W    = 112;
constexpr int C4   = 16;          // 64 floats = 16 float4 per pixel
constexpr int OH   = 224;
constexpr int OW   = 224;
constexpr int ROW4 = OW * C4;     // 3584 float4 per output row
constexpr int CHUNK = 512;        // float4 per block (2 per thread, 256 threads)

__global__ void __launch_bounds__(256)
unpool_zi_kernel(const float4* __restrict__ in, float4* __restrict__ out)
{
    const unsigned tid  = threadIdx.x;
    const unsigned oh   = blockIdx.y;
    const unsigned b    = blockIdx.z;
    const unsigned base = blockIdx.x * (unsigned)CHUNK + tid;

    float4* orow = out + (size_t)(b * OH + oh) * ROW4;

    const float4 z = make_float4(0.f, 0.f, 0.f, 0.f);

    if (oh & 1u) {
        // Entire row is zero: pure streaming store, no loads.
        __stcs(orow + base,        z);
        __stcs(orow + base + 256u, z);
        return;
    }

    const float4* irow = in + (size_t)(b * H + (oh >> 1)) * (W * C4);

    // Two independent elements per thread -> 2 outstanding loads before stores.
    const unsigned j0 = base;
    const unsigned j1 = base + 256u;

    const unsigned ow0 = j0 >> 4, c40 = j0 & 15u;
    const unsigned ow1 = j1 >> 4, c41 = j1 & 15u;

    float4 v0 = z, v1 = z;
    if (!(ow0 & 1u)) v0 = __ldcs(irow + (ow0 >> 1) * C4 + c40);
    if (!(ow1 & 1u)) v1 = __ldcs(irow + (ow1 >> 1) * C4 + c41);

    __stcs(orow + j0, v0);
    __stcs(orow + j1, v1);
}

extern "C" void kernel_launch(void* const* d_in, const int* in_sizes, int n_in,
                              void* d_out, int out_size)
{
    const float4* in  = (const float4*)d_in[0];
    float4*       out = (float4*)d_out;

    dim3 grid(ROW4 / CHUNK, OH, B);   // (7, 224, 32)
    unpool_zi_kernel<<<grid, 256>>>(in, out);
}